// round 14
// baseline (speedup 1.0000x reference)
#include <cuda_runtime.h>
#include <cuda_fp16.h>
#include <cstdint>

#define NV 50000
#define NE 800000
#define FIN 128
#define FH  128
#define FO  64

// ---------------- scratch (no allocs allowed) ----------------
static __device__ int    g_is64;
static __device__ int    g_deg   [NV];
static __device__ int    g_rowptr[NV + 1];
static __device__ int    g_pos   [NE];
static __device__ int    g_col   [NE];
static __device__ int    g_part  [256];
static __device__ __align__(16) __half g_hp1[(size_t)NV * FH];   // dinv-prescaled x@W1   (fp16)
static __device__ __align__(16) __half g_hp2[(size_t)NV * FO];   // dinv-prescaled h1@W2  (fp16)

// ---------------- edge-index dtype probe ----------------
// If edge_index is int64 (LE, values < 2^31), every odd int32 word is 0.
__global__ void probe_kernel(const int* __restrict__ raw, int* __restrict__ is64) {
    int v = raw[2 * threadIdx.x + 1];
    int any = __syncthreads_or(v != 0);
    if (threadIdx.x == 0) *is64 = (any == 0) ? 1 : 0;
}

// degrees + per-edge slot (deg pre-zeroed)
__global__ void count_deg_kernel(const int* __restrict__ raw, int e,
                                 const int* __restrict__ is64f,
                                 int* __restrict__ deg, int* __restrict__ pos) {
    int i = blockIdx.x * blockDim.x + threadIdx.x;
    if (i >= e) return;
    int d = (*is64f) ? raw[2 * ((size_t)e + i)] : raw[(size_t)e + i];
    pos[i] = atomicAdd(&deg[d], 1);
}

// ---------------- 3-phase scan ----------------
__global__ void scan_block_kernel(const int* __restrict__ deg, int n,
                                  int* __restrict__ rowptr, int* __restrict__ part)
{
    __shared__ int sm[1024];
    int i = blockIdx.x * 1024 + threadIdx.x;
    int v = (i < n) ? deg[i] : 0;
    sm[threadIdx.x] = v;
    __syncthreads();
    for (int off = 1; off < 1024; off <<= 1) {
        int t = (threadIdx.x >= (unsigned)off) ? sm[threadIdx.x - off] : 0;
        __syncthreads();
        sm[threadIdx.x] += t;
        __syncthreads();
    }
    if (i < n) rowptr[i] = sm[threadIdx.x] - v;      // block-local exclusive
    if (threadIdx.x == 1023) part[blockIdx.x] = sm[1023];
}

__global__ void scan_part_kernel(int* __restrict__ part, int nb,
                                 int* __restrict__ rowptr, int n)
{
    __shared__ int sm[256];
    int v = (threadIdx.x < (unsigned)nb) ? part[threadIdx.x] : 0;
    sm[threadIdx.x] = v;
    __syncthreads();
    for (int off = 1; off < 256; off <<= 1) {
        int t = (threadIdx.x >= (unsigned)off) ? sm[threadIdx.x - off] : 0;
        __syncthreads();
        sm[threadIdx.x] += t;
        __syncthreads();
    }
    if (threadIdx.x < (unsigned)nb) part[threadIdx.x] = sm[threadIdx.x] - v;  // exclusive
    if (threadIdx.x == 0) rowptr[n] = sm[255];
}

__global__ void add_off_kernel(const int* __restrict__ part, int n, int* __restrict__ rowptr)
{
    int i = blockIdx.x * blockDim.x + threadIdx.x;
    if (i < n) rowptr[i] += part[i >> 10];
}

// ---------------- CSR fill (atomic-free): col[rowptr[dst]+pos] = src ----------------
__global__ void fill_kernel(const int* __restrict__ raw, int e,
                            const int* __restrict__ is64f, const int* __restrict__ pos,
                            const int* __restrict__ rowptr, int* __restrict__ col)
{
    int i = blockIdx.x * blockDim.x + threadIdx.x;
    if (i >= e) return;
    int s, d;
    if (*is64f) {
        s = raw[2 * (size_t)i];
        d = raw[2 * ((size_t)e + i)];
    } else {
        s = raw[i];
        d = raw[(size_t)e + i];
    }
    col[__ldg(&rowptr[d]) + pos[i]] = s;
}

// ---------------- fp16 mma helper ----------------
__device__ __forceinline__ void mma_f16(float* d,
    uint32_t a0, uint32_t a1, uint32_t a2, uint32_t a3,
    uint32_t b0, uint32_t b1)
{
    asm volatile("mma.sync.aligned.m16n8k16.row.col.f32.f16.f16.f32 "
        "{%0,%1,%2,%3}, {%4,%5,%6,%7}, {%8,%9}, {%0,%1,%2,%3};"
        : "+f"(d[0]), "+f"(d[1]), "+f"(d[2]), "+f"(d[3])
        : "r"(a0), "r"(a1), "r"(a2), "r"(a3), "r"(b0), "r"(b1));
}

#define SKW (128 / 2 + 4)   // 68 words smem row stride

// ---------------- gemm1: hp1[row] = fp16( dinv[row] * (x[row] @ W1) ), fp32 input ----------------
__global__ __launch_bounds__(256) void gemm1_kernel(
    const float* __restrict__ A, const float* __restrict__ W,
    const int* __restrict__ deg, __half* __restrict__ hp, int n)
{
    constexpr int K = 128, OUT = 128, TILE_M = 64;
    constexpr int WM = 32, WN = 32, MT = 2, NT = 4, SK = SKW;

    extern __shared__ uint32_t smem[];
    uint32_t* Xs = smem;                  // [64][SK]
    uint32_t* Wt = smem + TILE_M * SK;    // [OUT][SK]

    const int t = threadIdx.x, lane = t & 31, wid = t >> 5;
    const int wm = wid % 2, wn = wid / 2;
    const int lr = lane >> 2, lc = lane & 3;
    const int row0 = blockIdx.x * TILE_M;

    for (int i = t; i < (K / 2) * OUT; i += 256) {
        int k2 = i / OUT, c = i % OUT;
        __half2 h = __floats2half2_rn(W[(size_t)(2 * k2) * OUT + c],
                                      W[(size_t)(2 * k2 + 1) * OUT + c]);
        Wt[c * SK + k2] = *(uint32_t*)&h;
    }
    const float4* A4 = (const float4*)A;
    for (int i = t; i < TILE_M * (K / 4); i += 256) {
        int r = i / (K / 4), c4 = i % (K / 4);
        int gr = row0 + r;
        float4 v = (gr < n) ? A4[(size_t)gr * (K / 4) + c4] : make_float4(0.f, 0.f, 0.f, 0.f);
        __half2 h0 = __floats2half2_rn(v.x, v.y);
        __half2 h1 = __floats2half2_rn(v.z, v.w);
        Xs[r * SK + c4 * 2]     = *(uint32_t*)&h0;
        Xs[r * SK + c4 * 2 + 1] = *(uint32_t*)&h1;
    }
    __syncthreads();

    float d[MT][NT][4];
#pragma unroll
    for (int mt = 0; mt < MT; mt++)
#pragma unroll
        for (int nt = 0; nt < NT; nt++)
            d[mt][nt][0] = d[mt][nt][1] = d[mt][nt][2] = d[mt][nt][3] = 0.f;

    const int r0 = wm * WM, c0 = wn * WN;
#pragma unroll
    for (int k0 = 0; k0 < K; k0 += 16) {
        const int w0 = k0 / 2;
        uint32_t b[NT][2];
#pragma unroll
        for (int nt = 0; nt < NT; nt++) {
            int bc = c0 + nt * 8 + lr;
            b[nt][0] = Wt[bc * SK + w0 + lc];
            b[nt][1] = Wt[bc * SK + w0 + 4 + lc];
        }
#pragma unroll
        for (int mt = 0; mt < MT; mt++) {
            int ar = r0 + mt * 16 + lr;
            uint32_t a0 = Xs[ar       * SK + w0 + lc];
            uint32_t a1 = Xs[(ar + 8) * SK + w0 + lc];
            uint32_t a2 = Xs[ar       * SK + w0 + 4 + lc];
            uint32_t a3 = Xs[(ar + 8) * SK + w0 + 4 + lc];
#pragma unroll
            for (int nt = 0; nt < NT; nt++)
                mma_f16(d[mt][nt], a0, a1, a2, a3, b[nt][0], b[nt][1]);
        }
    }

#pragma unroll
    for (int mt = 0; mt < MT; mt++) {
        int gr0 = row0 + r0 + mt * 16 + lr;
        int gr1 = gr0 + 8;
        float dv0 = (gr0 < n) ? rsqrtf((float)(deg[gr0] + 1)) : 0.f;
        float dv1 = (gr1 < n) ? rsqrtf((float)(deg[gr1] + 1)) : 0.f;
#pragma unroll
        for (int nt = 0; nt < NT; nt++) {
            int gc = c0 + nt * 8 + 2 * lc;
            if (gr0 < n) {
                __half2 h = __floats2half2_rn(d[mt][nt][0] * dv0, d[mt][nt][1] * dv0);
                ((uint32_t*)hp)[(size_t)gr0 * (OUT / 2) + gc / 2] = *(uint32_t*)&h;
            }
            if (gr1 < n) {
                __half2 h = __floats2half2_rn(d[mt][nt][2] * dv1, d[mt][nt][3] * dv1);
                ((uint32_t*)hp)[(size_t)gr1 * (OUT / 2) + gc / 2] = *(uint32_t*)&h;
            }
        }
    }
}

// ---------------- fused agg1 + gemm2 ----------------
// Block owns 64 nodes: phase1 aggregates h1 rows (relu'd, fp16) into Xs smem;
// phase2 computes hp2 = fp16( dinv * (h1tile @ W2) ).
__device__ __forceinline__ void acc8(float* a, uint4 v) {
    const __half2* ph = (const __half2*)&v;
#pragma unroll
    for (int j = 0; j < 4; j++) {
        float2 f = __half22float2(ph[j]);
        a[2 * j]     += f.x;
        a[2 * j + 1] += f.y;
    }
}

__global__ __launch_bounds__(256) void agg_gemm2_kernel(
    const int* __restrict__ rowptr, const int* __restrict__ col,
    const __half* __restrict__ hp1, const int* __restrict__ deg,
    const float* __restrict__ b1, const float* __restrict__ W2,
    __half* __restrict__ hp2, int n)
{
    constexpr int K = 128, OUT = 64, TILE_M = 64;
    constexpr int WM = 32, WN = 16, MT = 2, NT = 2, SK = SKW;

    extern __shared__ uint32_t smem[];
    uint32_t* Xs = smem;                  // [64][SK] : aggregated h1 tile (half2)
    uint32_t* Wt = smem + TILE_M * SK;    // [OUT][SK]

    const int t = threadIdx.x, lane = t & 31, wid = t >> 5;
    const int row0 = blockIdx.x * TILE_M;

    // W2 [K][OUT] fp32 -> Wt [OUT][K/2] half2 (transpose)
    for (int i = t; i < (K / 2) * OUT; i += 256) {
        int k2 = i / OUT, c = i % OUT;
        __half2 h = __floats2half2_rn(W2[(size_t)(2 * k2) * OUT + c],
                                      W2[(size_t)(2 * k2 + 1) * OUT + c]);
        Wt[c * SK + k2] = *(uint32_t*)&h;
    }

    // phase 1: aggregate 64 nodes (2 nodes/warp x 4 reps), write h1 into Xs
    {
        const uint4* hp4 = (const uint4*)hp1;
        const int li  = lane & 15;             // 16 lanes per node, 8 feats each
        const int sub = lane >> 4;             // 0 or 1
#pragma unroll
        for (int rep = 0; rep < 4; rep++) {
            int ln   = rep * 16 + wid * 2 + sub;
            int node = row0 + ln;
            float a0[8] = {0,0,0,0,0,0,0,0};
            float a1[8] = {0,0,0,0,0,0,0,0};
            if (node < n) {
                acc8(a0, hp4[(size_t)node * 16 + li]);   // self (prescaled)
                int e  = rowptr[node];
                int e1 = rowptr[node + 1];
                for (; e + 8 <= e1; e += 8) {
                    int s0 = __ldg(&col[e]);     int s1 = __ldg(&col[e + 1]);
                    int s2 = __ldg(&col[e + 2]); int s3 = __ldg(&col[e + 3]);
                    int s4 = __ldg(&col[e + 4]); int s5 = __ldg(&col[e + 5]);
                    int s6 = __ldg(&col[e + 6]); int s7 = __ldg(&col[e + 7]);
                    uint4 v0 = hp4[(size_t)s0 * 16 + li];
                    uint4 v1 = hp4[(size_t)s1 * 16 + li];
                    uint4 v2 = hp4[(size_t)s2 * 16 + li];
                    uint4 v3 = hp4[(size_t)s3 * 16 + li];
                    uint4 v4 = hp4[(size_t)s4 * 16 + li];
                    uint4 v5 = hp4[(size_t)s5 * 16 + li];
                    uint4 v6 = hp4[(size_t)s6 * 16 + li];
                    uint4 v7 = hp4[(size_t)s7 * 16 + li];
                    acc8(a0, v0); acc8(a1, v1); acc8(a0, v2); acc8(a1, v3);
                    acc8(a0, v4); acc8(a1, v5); acc8(a0, v6); acc8(a1, v7);
                }
                for (; e + 2 <= e1; e += 2) {
                    int s0 = __ldg(&col[e]);
                    int s1 = __ldg(&col[e + 1]);
                    uint4 v0 = hp4[(size_t)s0 * 16 + li];
                    uint4 v1 = hp4[(size_t)s1 * 16 + li];
                    acc8(a0, v0); acc8(a1, v1);
                }
                for (; e < e1; e++)
                    acc8(a0, hp4[(size_t)__ldg(&col[e]) * 16 + li]);
#pragma unroll
                for (int j = 0; j < 8; j++) a0[j] += a1[j];

                float dv = rsqrtf((float)(deg[node] + 1));
                const float4* b4 = (const float4*)b1;
                float4 bv0 = b4[li * 2];
                float4 bv1 = b4[li * 2 + 1];
                float o[8];
                o[0] = fmaxf(fmaf(a0[0], dv, bv0.x), 0.f);
                o[1] = fmaxf(fmaf(a0[1], dv, bv0.y), 0.f);
                o[2] = fmaxf(fmaf(a0[2], dv, bv0.z), 0.f);
                o[3] = fmaxf(fmaf(a0[3], dv, bv0.w), 0.f);
                o[4] = fmaxf(fmaf(a0[4], dv, bv1.x), 0.f);
                o[5] = fmaxf(fmaf(a0[5], dv, bv1.y), 0.f);
                o[6] = fmaxf(fmaf(a0[6], dv, bv1.z), 0.f);
                o[7] = fmaxf(fmaf(a0[7], dv, bv1.w), 0.f);
                __half2 h0 = __floats2half2_rn(o[0], o[1]);
                __half2 h1h = __floats2half2_rn(o[2], o[3]);
                __half2 h2 = __floats2half2_rn(o[4], o[5]);
                __half2 h3 = __floats2half2_rn(o[6], o[7]);
                uint32_t* p = &Xs[ln * SK + li * 4];
                p[0] = *(uint32_t*)&h0; p[1] = *(uint32_t*)&h1h;
                p[2] = *(uint32_t*)&h2; p[3] = *(uint32_t*)&h3;
            } else {
                uint32_t* p = &Xs[ln * SK + li * 4];
                p[0] = 0; p[1] = 0; p[2] = 0; p[3] = 0;
            }
        }
    }
    __syncthreads();

    // phase 2: MMA h1tile @ W2
    const int wm = wid % 2, wn = wid / 2;
    const int lr = lane >> 2, lc = lane & 3;

    float d[MT][NT][4];
#pragma unroll
    for (int mt = 0; mt < MT; mt++)
#pragma unroll
        for (int nt = 0; nt < NT; nt++)
            d[mt][nt][0] = d[mt][nt][1] = d[mt][nt][2] = d[mt][nt][3] = 0.f;

    const int r0 = wm * WM, c0 = wn * WN;
#pragma unroll
    for (int k0 = 0; k0 < K; k0 += 16) {
        const int w0 = k0 / 2;
        uint32_t b[NT][2];
#pragma unroll
        for (int nt = 0; nt < NT; nt++) {
            int bc = c0 + nt * 8 + lr;
            b[nt][0] = Wt[bc * SK + w0 + lc];
            b[nt][1] = Wt[bc * SK + w0 + 4 + lc];
        }
#pragma unroll
        for (int mt = 0; mt < MT; mt++) {
            int ar = r0 + mt * 16 + lr;
            uint32_t a0 = Xs[ar       * SK + w0 + lc];
            uint32_t a1 = Xs[(ar + 8) * SK + w0 + lc];
            uint32_t a2 = Xs[ar       * SK + w0 + 4 + lc];
            uint32_t a3 = Xs[(ar + 8) * SK + w0 + 4 + lc];
#pragma unroll
            for (int nt = 0; nt < NT; nt++)
                mma_f16(d[mt][nt], a0, a1, a2, a3, b[nt][0], b[nt][1]);
        }
    }

#pragma unroll
    for (int mt = 0; mt < MT; mt++) {
        int gr0 = row0 + r0 + mt * 16 + lr;
        int gr1 = gr0 + 8;
        float dv0 = (gr0 < n) ? rsqrtf((float)(deg[gr0] + 1)) : 0.f;
        float dv1 = (gr1 < n) ? rsqrtf((float)(deg[gr1] + 1)) : 0.f;
#pragma unroll
        for (int nt = 0; nt < NT; nt++) {
            int gc = c0 + nt * 8 + 2 * lc;
            if (gr0 < n) {
                __half2 h = __floats2half2_rn(d[mt][nt][0] * dv0, d[mt][nt][1] * dv0);
                ((uint32_t*)hp2)[(size_t)gr0 * (OUT / 2) + gc / 2] = *(uint32_t*)&h;
            }
            if (gr1 < n) {
                __half2 h = __floats2half2_rn(d[mt][nt][2] * dv1, d[mt][nt][3] * dv1);
                ((uint32_t*)hp2)[(size_t)gr1 * (OUT / 2) + gc / 2] = *(uint32_t*)&h;
            }
        }
    }
}

// ---------------- agg2: out[d] = dinv[d]*(hp2[d] + sum hp2[src]) + b2  (fp32 out) ----------------
__global__ __launch_bounds__(256) void aggregate2_kernel(
    const int* __restrict__ rowptr, const int* __restrict__ col,
    const __half* __restrict__ hp, const int* __restrict__ deg,
    const float* __restrict__ b, float* __restrict__ out, int n)
{
    constexpr int LPR = 8;            // 8 lanes per node (64 feats / 8)
    const int warp = (blockIdx.x * blockDim.x + threadIdx.x) >> 5;
    const int lane = threadIdx.x & 31;
    const int node = warp * 4 + lane / LPR;
    const int li   = lane % LPR;
    if (node >= n) return;

    const uint4* hp4 = (const uint4*)hp;

    float a0[8] = {0,0,0,0,0,0,0,0};
    float a1[8] = {0,0,0,0,0,0,0,0};

    acc8(a0, hp4[(size_t)node * LPR + li]);

    int e  = rowptr[node];
    int e1 = rowptr[node + 1];

    for (; e + 8 <= e1; e += 8) {
        int s0 = __ldg(&col[e]);     int s1 = __ldg(&col[e + 1]);
        int s2 = __ldg(&col[e + 2]); int s3 = __ldg(&col[e + 3]);
        int s4 = __ldg(&col[e + 4]); int s5 = __ldg(&col[e + 5]);
        int s6 = __ldg(&col[e + 6]); int s7 = __ldg(&col[e + 7]);
        uint4 v0 = hp4[(size_t)s0 * LPR + li];
        uint4 v1 = hp4[(size_t)s1 * LPR + li];
        uint4 v2 = hp4[(size_t)s2 * LPR + li];
        uint4 v3 = hp4[(size_t)s3 * LPR + li];
        uint4 v4 = hp4[(size_t)s4 * LPR + li];
        uint4 v5 = hp4[(size_t)s5 * LPR + li];
        uint4 v6 = hp4[(size_t)s6 * LPR + li];
        uint4 v7 = hp4[(size_t)s7 * LPR + li];
        acc8(a0, v0); acc8(a1, v1); acc8(a0, v2); acc8(a1, v3);
        acc8(a0, v4); acc8(a1, v5); acc8(a0, v6); acc8(a1, v7);
    }
    for (; e + 2 <= e1; e += 2) {
        int s0 = __ldg(&col[e]);
        int s1 = __ldg(&col[e + 1]);
        uint4 v0 = hp4[(size_t)s0 * LPR + li];
        uint4 v1 = hp4[(size_t)s1 * LPR + li];
        acc8(a0, v0); acc8(a1, v1);
    }
    for (; e < e1; e++)
        acc8(a0, hp4[(size_t)__ldg(&col[e]) * LPR + li]);
#pragma unroll
    for (int j = 0; j < 8; j++) a0[j] += a1[j];

    float dv = rsqrtf((float)(deg[node] + 1));
    const float4* b4 = (const float4*)b;
    float4 bv0 = b4[li * 2];
    float4 bv1 = b4[li * 2 + 1];
    float4 o0, o1;
    o0.x = fmaf(a0[0], dv, bv0.x);
    o0.y = fmaf(a0[1], dv, bv0.y);
    o0.z = fmaf(a0[2], dv, bv0.z);
    o0.w = fmaf(a0[3], dv, bv0.w);
    o1.x = fmaf(a0[4], dv, bv1.x);
    o1.y = fmaf(a0[5], dv, bv1.y);
    o1.z = fmaf(a0[6], dv, bv1.z);
    o1.w = fmaf(a0[7], dv, bv1.w);
    float4* out4 = (float4*)out;
    out4[(size_t)node * 16 + li * 2]     = o0;
    out4[(size_t)node * 16 + li * 2 + 1] = o1;
}

// ---------------- launcher ----------------
extern "C" void kernel_launch(void* const* d_in, const int* in_sizes, int n_in,
                              void* d_out, int out_size)
{
    const float* x   = (const float*)d_in[0];
    const int*   ei  = (const int*)d_in[1];     // int32 OR int64 raw words (probed)
    const float* W1  = (const float*)d_in[2];
    const float* b1  = (const float*)d_in[3];
    const float* W2  = (const float*)d_in[4];
    const float* b2  = (const float*)d_in[5];
    float*       out = (float*)d_out;

    const int n = in_sizes[0] / FIN;   // 50000
    const int e = in_sizes[1] / 2;     // 800000

    void *p_is64, *p_deg, *p_rowptr, *p_pos, *p_col, *p_part, *p_hp1, *p_hp2;
    cudaGetSymbolAddress(&p_is64,   g_is64);
    cudaGetSymbolAddress(&p_deg,    g_deg);
    cudaGetSymbolAddress(&p_rowptr, g_rowptr);
    cudaGetSymbolAddress(&p_pos,    g_pos);
    cudaGetSymbolAddress(&p_col,    g_col);
    cudaGetSymbolAddress(&p_part,   g_part);
    cudaGetSymbolAddress(&p_hp1,    g_hp1);
    cudaGetSymbolAddress(&p_hp2,    g_hp2);
    int*    is64   = (int*)p_is64;
    int*    deg    = (int*)p_deg;
    int*    rowptr = (int*)p_rowptr;
    int*    pos    = (int*)p_pos;
    int*    col    = (int*)p_col;
    int*    part   = (int*)p_part;
    __half* hp1    = (__half*)p_hp1;
    __half* hp2    = (__half*)p_hp2;

    // one-time side stream + events (created on first, non-captured, call)
    static cudaStream_t s_side = nullptr;
    static cudaEvent_t  ev_fork = nullptr, ev_join = nullptr;
    if (s_side == nullptr) {
        cudaStreamCreateWithFlags(&s_side, cudaStreamNonBlocking);
        cudaEventCreateWithFlags(&ev_fork, cudaEventDisableTiming);
        cudaEventCreateWithFlags(&ev_join, cudaEventDisableTiming);
    }

    const int smem1 = (64 * SKW + FH * SKW) * (int)sizeof(uint32_t);  // 52224
    const int smem2 = (64 * SKW + FO * SKW) * (int)sizeof(uint32_t);  // 34816
    cudaFuncSetAttribute((const void*)gemm1_kernel,     cudaFuncAttributeMaxDynamicSharedMemorySize, smem1);
    cudaFuncSetAttribute((const void*)agg_gemm2_kernel, cudaFuncAttributeMaxDynamicSharedMemorySize, smem2);

    const int nb = (n + 1023) / 1024;

    // ---- main: probe + degrees (+ per-edge slots) ----
    cudaMemsetAsync(deg, 0, n * sizeof(int));
    probe_kernel     <<<1, 256>>>(ei, is64);
    count_deg_kernel <<<(e + 255) / 256, 256>>>(ei, e, is64, deg, pos);

    // ---- fork: CSR build on side stream ----
    cudaEventRecord(ev_fork, 0);
    cudaStreamWaitEvent(s_side, ev_fork, 0);
    scan_block_kernel<<<nb, 1024, 0, s_side>>>(deg, n, rowptr, part);
    scan_part_kernel <<<1, 256, 0, s_side>>>(part, nb, rowptr, n);
    add_off_kernel   <<<(n + 255) / 256, 256, 0, s_side>>>(part, n, rowptr);
    fill_kernel      <<<(e + 255) / 256, 256, 0, s_side>>>(ei, e, is64, pos, rowptr, col);
    cudaEventRecord(ev_join, s_side);

    // ---- main: gemm1 (needs only deg) ----
    gemm1_kernel<<<(n + 63) / 64, 256, smem1>>>(x, W1, deg, hp1, n);

    // ---- join, then fused agg1+gemm2, then agg2 ----
    cudaStreamWaitEvent(0, ev_join, 0);
    agg_gemm2_kernel<<<(n + 63) / 64, 256, smem2>>>(rowptr, col, hp1, deg, b1, W2, hp2, n);
    {
        int warps = (n + 3) / 4;
        aggregate2_kernel<<<(warps * 32 + 255) / 256, 256>>>(rowptr, col, hp2, deg, b2, out, n);
    }
}

// round 15
// speedup vs baseline: 1.0871x; 1.0871x over previous
#include <cuda_runtime.h>
#include <cuda_fp16.h>
#include <cstdint>

#define NV 50000
#define NE 800000
#define FIN 128
#define FH  128
#define FO  64

// ---------------- scratch (no allocs allowed) ----------------
static __device__ int    g_deg   [NV];
static __device__ int    g_rowptr[NV + 1];
static __device__ int    g_cursor[NV];
static __device__ int    g_col   [NE];
static __device__ int    g_part  [256];
static __device__ __align__(16) __half g_hp1[(size_t)NV * FH];   // dinv-prescaled x@W1   (fp16)
static __device__ __align__(16) __half g_h1 [(size_t)NV * FH];   // layer-1 activation    (fp16)
static __device__ __align__(16) __half g_hp2[(size_t)NV * FO];   // dinv-prescaled h1@W2  (fp16)

// ---------------- inline edge-index dtype probe ----------------
// If edge_index is int64 (LE, values < 2^31), every odd int32 word is 0.
// Per-block redundant decision from the first 256 pairs (L2-cached; measured free).
__device__ __forceinline__ int probe_is64(const int* __restrict__ raw) {
    __shared__ int anynz;
    if (threadIdx.x == 0) anynz = 0;
    __syncthreads();
    if (threadIdx.x < 256) {
        int v = __ldg(&raw[2 * threadIdx.x + 1]);
        if (v != 0) atomicOr(&anynz, 1);
    }
    __syncthreads();
    return anynz == 0;
}

// count dst degrees, 4 edges/thread for atomic MLP (deg pre-zeroed)
__global__ void count_deg_kernel(const int* __restrict__ raw, int e, int* __restrict__ deg) {
    int is64 = probe_is64(raw);
    int base = blockIdx.x * (blockDim.x * 4) + threadIdx.x;
#pragma unroll
    for (int j = 0; j < 4; j++) {
        int i = base + j * blockDim.x;
        if (i < e) {
            int d = is64 ? raw[2 * ((size_t)e + i)] : raw[(size_t)e + i];
            atomicAdd(&deg[d], 1);
        }
    }
}

// ---------------- 3-phase scan ----------------
__global__ void scan_block_kernel(const int* __restrict__ deg, int n,
                                  int* __restrict__ rowptr, int* __restrict__ part)
{
    __shared__ int sm[1024];
    int i = blockIdx.x * 1024 + threadIdx.x;
    int v = (i < n) ? deg[i] : 0;
    sm[threadIdx.x] = v;
    __syncthreads();
    for (int off = 1; off < 1024; off <<= 1) {
        int t = (threadIdx.x >= (unsigned)off) ? sm[threadIdx.x - off] : 0;
        __syncthreads();
        sm[threadIdx.x] += t;
        __syncthreads();
    }
    if (i < n) rowptr[i] = sm[threadIdx.x] - v;      // block-local exclusive
    if (threadIdx.x == 1023) part[blockIdx.x] = sm[1023];
}

__global__ void scan_part_kernel(int* __restrict__ part, int nb,
                                 int* __restrict__ rowptr, int n)
{
    __shared__ int sm[256];
    int v = (threadIdx.x < (unsigned)nb) ? part[threadIdx.x] : 0;
    sm[threadIdx.x] = v;
    __syncthreads();
    for (int off = 1; off < 256; off <<= 1) {
        int t = (threadIdx.x >= (unsigned)off) ? sm[threadIdx.x - off] : 0;
        __syncthreads();
        sm[threadIdx.x] += t;
        __syncthreads();
    }
    if (threadIdx.x < (unsigned)nb) part[threadIdx.x] = sm[threadIdx.x] - v;  // exclusive
    if (threadIdx.x == 0) rowptr[n] = sm[255];
}

__global__ void add_off_kernel(const int* __restrict__ part, int n,
                               int* __restrict__ rowptr, int* __restrict__ cursor)
{
    int i = blockIdx.x * blockDim.x + threadIdx.x;
    if (i < n) {
        int r = rowptr[i] + part[i >> 10];
        rowptr[i] = r;
        cursor[i] = r;
    }
}

// ---------------- CSR fill: col[pos] = src, 4 edges/thread for atomic MLP ----------------
__global__ void fill_kernel(const int* __restrict__ raw, int e,
                            int* __restrict__ cursor, int* __restrict__ col)
{
    int is64 = probe_is64(raw);
    int base = blockIdx.x * (blockDim.x * 4) + threadIdx.x;
    int s[4], d[4];
    bool ok[4];
#pragma unroll
    for (int j = 0; j < 4; j++) {
        int i = base + j * blockDim.x;
        ok[j] = (i < e);
        if (ok[j]) {
            if (is64) {
                s[j] = raw[2 * (size_t)i];
                d[j] = raw[2 * ((size_t)e + i)];
            } else {
                s[j] = raw[i];
                d[j] = raw[(size_t)e + i];
            }
        }
    }
    int pos[4];
#pragma unroll
    for (int j = 0; j < 4; j++)
        if (ok[j]) pos[j] = atomicAdd(&cursor[d[j]], 1);
#pragma unroll
    for (int j = 0; j < 4; j++)
        if (ok[j]) col[pos[j]] = s[j];
}

// ---------------- fp16 mma helper ----------------
__device__ __forceinline__ void mma_f16(float* d,
    uint32_t a0, uint32_t a1, uint32_t a2, uint32_t a3,
    uint32_t b0, uint32_t b1)
{
    asm volatile("mma.sync.aligned.m16n8k16.row.col.f32.f16.f16.f32 "
        "{%0,%1,%2,%3}, {%4,%5,%6,%7}, {%8,%9}, {%0,%1,%2,%3};"
        : "+f"(d[0]), "+f"(d[1]), "+f"(d[2]), "+f"(d[3])
        : "r"(a0), "r"(a1), "r"(a2), "r"(a3), "r"(b0), "r"(b1));
}

// ---------------- fp16 tensor-core GEMM: hp[row] = fp16( dinv[row] * (A[row] @ W) ) ----------------
// Block tile 64 x OUT, K=128, 8 warps. A fp32 or fp16 per IN_HALF.
template<int OUT, bool IN_HALF>
__global__ __launch_bounds__(256) void gemm_f16_kernel(
    const void* __restrict__ Ain, const float* __restrict__ W,
    const int* __restrict__ deg, __half* __restrict__ hp, int n)
{
    constexpr int K       = 128;
    constexpr int TILE_M  = 64;
    constexpr int WARPS_M = 2;
    constexpr int WM      = TILE_M / WARPS_M;  // 32
    constexpr int WN      = OUT / 4;           // 32 or 16
    constexpr int MT      = WM / 16;           // 2
    constexpr int NT      = WN / 8;            // 4 or 2
    constexpr int SK      = K / 2 + 4;         // 68 words

    extern __shared__ uint32_t smem[];
    uint32_t* Xs = smem;                  // [TILE_M][SK]
    uint32_t* Wt = smem + TILE_M * SK;    // [OUT][SK]

    const int t    = threadIdx.x;
    const int lane = t & 31;
    const int wid  = t >> 5;
    const int wm   = wid % WARPS_M;
    const int wn   = wid / WARPS_M;
    const int lr   = lane >> 2;
    const int lc   = lane & 3;

    const int row0 = blockIdx.x * TILE_M;

    // W [K][OUT] fp32 -> Wt [OUT][K/2] packed half2 (transpose)
    for (int i = t; i < (K / 2) * OUT; i += 256) {
        int k2 = i / OUT;
        int c  = i % OUT;
        __half2 h = __floats2half2_rn(W[(size_t)(2 * k2) * OUT + c],
                                      W[(size_t)(2 * k2 + 1) * OUT + c]);
        Wt[c * SK + k2] = *(uint32_t*)&h;
    }
    if (IN_HALF) {
        const uint4* A8 = (const uint4*)Ain;
        for (int i = t; i < TILE_M * (K / 8); i += 256) {
            int r  = i / (K / 8);
            int c8 = i % (K / 8);
            int gr = row0 + r;
            uint32_t* p = &Xs[r * SK + c8 * 4];
            if (gr < n) {
                uint4 v = A8[(size_t)gr * (K / 8) + c8];
                p[0] = v.x; p[1] = v.y; p[2] = v.z; p[3] = v.w;
            } else {
                p[0] = 0; p[1] = 0; p[2] = 0; p[3] = 0;
            }
        }
    } else {
        const float4* A4 = (const float4*)Ain;
        for (int i = t; i < TILE_M * (K / 4); i += 256) {
            int r  = i / (K / 4);
            int c4 = i % (K / 4);
            int gr = row0 + r;
            float4 v = (gr < n) ? A4[(size_t)gr * (K / 4) + c4]
                                : make_float4(0.f, 0.f, 0.f, 0.f);
            __half2 h0 = __floats2half2_rn(v.x, v.y);
            __half2 h1 = __floats2half2_rn(v.z, v.w);
            Xs[r * SK + c4 * 2]     = *(uint32_t*)&h0;
            Xs[r * SK + c4 * 2 + 1] = *(uint32_t*)&h1;
        }
    }
    __syncthreads();

    float d[MT][NT][4];
#pragma unroll
    for (int mt = 0; mt < MT; mt++)
#pragma unroll
        for (int nt = 0; nt < NT; nt++) {
            d[mt][nt][0] = 0.f; d[mt][nt][1] = 0.f;
            d[mt][nt][2] = 0.f; d[mt][nt][3] = 0.f;
        }

    const int r0 = wm * WM;
    const int c0 = wn * WN;

#pragma unroll
    for (int k0 = 0; k0 < K; k0 += 16) {
        const int w0 = k0 / 2;
        uint32_t b[NT][2];
#pragma unroll
        for (int nt = 0; nt < NT; nt++) {
            int bc = c0 + nt * 8 + lr;
            b[nt][0] = Wt[bc * SK + w0 + lc];
            b[nt][1] = Wt[bc * SK + w0 + 4 + lc];
        }
#pragma unroll
        for (int mt = 0; mt < MT; mt++) {
            int ar = r0 + mt * 16 + lr;
            uint32_t a0 = Xs[ar       * SK + w0 + lc];
            uint32_t a1 = Xs[(ar + 8) * SK + w0 + lc];
            uint32_t a2 = Xs[ar       * SK + w0 + 4 + lc];
            uint32_t a3 = Xs[(ar + 8) * SK + w0 + 4 + lc];
#pragma unroll
            for (int nt = 0; nt < NT; nt++)
                mma_f16(d[mt][nt], a0, a1, a2, a3, b[nt][0], b[nt][1]);
        }
    }

#pragma unroll
    for (int mt = 0; mt < MT; mt++) {
        int gr0 = row0 + r0 + mt * 16 + lr;
        int gr1 = gr0 + 8;
        float dv0 = (gr0 < n) ? rsqrtf((float)(deg[gr0] + 1)) : 0.f;
        float dv1 = (gr1 < n) ? rsqrtf((float)(deg[gr1] + 1)) : 0.f;
#pragma unroll
        for (int nt = 0; nt < NT; nt++) {
            int gc = c0 + nt * 8 + 2 * lc;
            if (gr0 < n) {
                __half2 h = __floats2half2_rn(d[mt][nt][0] * dv0, d[mt][nt][1] * dv0);
                ((uint32_t*)hp)[(size_t)gr0 * (OUT / 2) + gc / 2] = *(uint32_t*)&h;
            }
            if (gr1 < n) {
                __half2 h = __floats2half2_rn(d[mt][nt][2] * dv1, d[mt][nt][3] * dv1);
                ((uint32_t*)hp)[(size_t)gr1 * (OUT / 2) + gc / 2] = *(uint32_t*)&h;
            }
        }
    }
}

// ---------------- aggregate: out[d] = act(dinv[d]*(hp[d] + sum_src hp[src]) + b) ----------------
__device__ __forceinline__ void acc8(float* a, uint4 v) {
    const __half2* ph = (const __half2*)&v;
#pragma unroll
    for (int j = 0; j < 4; j++) {
        float2 f = __half22float2(ph[j]);
        a[2 * j]     += f.x;
        a[2 * j + 1] += f.y;
    }
}

template<int F, bool RELU, bool OUT_HALF>
__global__ __launch_bounds__(256) void aggregate_kernel(
    const int* __restrict__ rowptr, const int* __restrict__ col,
    const __half* __restrict__ hp, const int* __restrict__ deg,
    const float* __restrict__ b, void* __restrict__ out, int n)
{
    constexpr int LPR = F / 8;        // lanes per node row (16 or 8)
    constexpr int SUB = 32 / LPR;     // nodes per warp (2 or 4)
    const int warp = (blockIdx.x * blockDim.x + threadIdx.x) >> 5;
    const int lane = threadIdx.x & 31;
    const int node = warp * SUB + lane / LPR;
    const int li   = lane % LPR;
    if (node >= n) return;

    const uint4* hp4 = (const uint4*)hp;

    float a0[8] = {0,0,0,0,0,0,0,0};
    float a1[8] = {0,0,0,0,0,0,0,0};

    acc8(a0, hp4[(size_t)node * LPR + li]);   // self-loop term (prescaled)

    int e  = rowptr[node];
    int e1 = rowptr[node + 1];

    for (; e + 8 <= e1; e += 8) {
        int s0 = __ldg(&col[e]);
        int s1 = __ldg(&col[e + 1]);
        int s2 = __ldg(&col[e + 2]);
        int s3 = __ldg(&col[e + 3]);
        int s4 = __ldg(&col[e + 4]);
        int s5 = __ldg(&col[e + 5]);
        int s6 = __ldg(&col[e + 6]);
        int s7 = __ldg(&col[e + 7]);
        uint4 v0 = hp4[(size_t)s0 * LPR + li];
        uint4 v1 = hp4[(size_t)s1 * LPR + li];
        uint4 v2 = hp4[(size_t)s2 * LPR + li];
        uint4 v3 = hp4[(size_t)s3 * LPR + li];
        uint4 v4 = hp4[(size_t)s4 * LPR + li];
        uint4 v5 = hp4[(size_t)s5 * LPR + li];
        uint4 v6 = hp4[(size_t)s6 * LPR + li];
        uint4 v7 = hp4[(size_t)s7 * LPR + li];
        acc8(a0, v0); acc8(a1, v1); acc8(a0, v2); acc8(a1, v3);
        acc8(a0, v4); acc8(a1, v5); acc8(a0, v6); acc8(a1, v7);
    }
    for (; e + 2 <= e1; e += 2) {
        int s0 = __ldg(&col[e]);
        int s1 = __ldg(&col[e + 1]);
        uint4 v0 = hp4[(size_t)s0 * LPR + li];
        uint4 v1 = hp4[(size_t)s1 * LPR + li];
        acc8(a0, v0); acc8(a1, v1);
    }
    for (; e < e1; e++) {
        acc8(a0, hp4[(size_t)__ldg(&col[e]) * LPR + li]);
    }
#pragma unroll
    for (int j = 0; j < 8; j++) a0[j] += a1[j];

    float dv = rsqrtf((float)(deg[node] + 1));
    const float4* b4 = (const float4*)b;
    float4 bv0 = b4[li * 2];
    float4 bv1 = b4[li * 2 + 1];
    float o[8];
    o[0] = fmaf(a0[0], dv, bv0.x);
    o[1] = fmaf(a0[1], dv, bv0.y);
    o[2] = fmaf(a0[2], dv, bv0.z);
    o[3] = fmaf(a0[3], dv, bv0.w);
    o[4] = fmaf(a0[4], dv, bv1.x);
    o[5] = fmaf(a0[5], dv, bv1.y);
    o[6] = fmaf(a0[6], dv, bv1.z);
    o[7] = fmaf(a0[7], dv, bv1.w);
    if (RELU) {
#pragma unroll
        for (int j = 0; j < 8; j++) o[j] = fmaxf(o[j], 0.f);
    }
    if (OUT_HALF) {
        __half2 h0 = __floats2half2_rn(o[0], o[1]);
        __half2 h1 = __floats2half2_rn(o[2], o[3]);
        __half2 h2 = __floats2half2_rn(o[4], o[5]);
        __half2 h3 = __floats2half2_rn(o[6], o[7]);
        uint4 pk;
        pk.x = *(uint32_t*)&h0; pk.y = *(uint32_t*)&h1;
        pk.z = *(uint32_t*)&h2; pk.w = *(uint32_t*)&h3;
        ((uint4*)out)[(size_t)node * LPR + li] = pk;
    } else {
        float4* out4 = (float4*)out;
        out4[(size_t)node * (F / 4) + li * 2]     = make_float4(o[0], o[1], o[2], o[3]);
        out4[(size_t)node * (F / 4) + li * 2 + 1] = make_float4(o[4], o[5], o[6], o[7]);
    }
}

// ---------------- launcher ----------------
extern "C" void kernel_launch(void* const* d_in, const int* in_sizes, int n_in,
                              void* d_out, int out_size)
{
    const float* x   = (const float*)d_in[0];
    const int*   ei  = (const int*)d_in[1];     // int32 OR int64 raw words (probed per-block)
    const float* W1  = (const float*)d_in[2];
    const float* b1  = (const float*)d_in[3];
    const float* W2  = (const float*)d_in[4];
    const float* b2  = (const float*)d_in[5];
    float*       out = (float*)d_out;

    const int n = in_sizes[0] / FIN;   // 50000
    const int e = in_sizes[1] / 2;     // 800000

    void *p_deg, *p_rowptr, *p_cursor, *p_col, *p_part, *p_hp1, *p_h1, *p_hp2;
    cudaGetSymbolAddress(&p_deg,    g_deg);
    cudaGetSymbolAddress(&p_rowptr, g_rowptr);
    cudaGetSymbolAddress(&p_cursor, g_cursor);
    cudaGetSymbolAddress(&p_col,    g_col);
    cudaGetSymbolAddress(&p_part,   g_part);
    cudaGetSymbolAddress(&p_hp1,    g_hp1);
    cudaGetSymbolAddress(&p_h1,     g_h1);
    cudaGetSymbolAddress(&p_hp2,    g_hp2);
    int*    deg    = (int*)p_deg;
    int*    rowptr = (int*)p_rowptr;
    int*    cursor = (int*)p_cursor;
    int*    col    = (int*)p_col;
    int*    part   = (int*)p_part;
    __half* hp1    = (__half*)p_hp1;
    __half* h1     = (__half*)p_h1;
    __half* hp2    = (__half*)p_hp2;

    // one-time side stream + events (created on first, non-captured, call)
    static cudaStream_t s_side = nullptr;
    static cudaEvent_t  ev_fork = nullptr, ev_join = nullptr;
    if (s_side == nullptr) {
        cudaStreamCreateWithFlags(&s_side, cudaStreamNonBlocking);
        cudaEventCreateWithFlags(&ev_fork, cudaEventDisableTiming);
        cudaEventCreateWithFlags(&ev_join, cudaEventDisableTiming);
    }

    constexpr int SK = 128 / 2 + 4;   // 68
    const int smem1 = (64 * SK + FH * SK) * (int)sizeof(uint32_t);  // 52224
    const int smem2 = (64 * SK + FO * SK) * (int)sizeof(uint32_t);  // 34816
    cudaFuncSetAttribute((const void*)gemm_f16_kernel<FH, false>, cudaFuncAttributeMaxDynamicSharedMemorySize, smem1);
    cudaFuncSetAttribute((const void*)gemm_f16_kernel<FO, true>,  cudaFuncAttributeMaxDynamicSharedMemorySize, smem2);

    const int nb = (n + 1023) / 1024;
    const int eb4 = (e + 1023) / 1024;   // 4 edges/thread @ 256 threads

    // ---- main: degrees (probe inlined) ----
    cudaMemsetAsync(deg, 0, n * sizeof(int));
    count_deg_kernel<<<eb4, 256>>>(ei, e, deg);

    // ---- fork: CSR build on side stream ----
    cudaEventRecord(ev_fork, 0);
    cudaStreamWaitEvent(s_side, ev_fork, 0);
    scan_block_kernel<<<nb, 1024, 0, s_side>>>(deg, n, rowptr, part);
    scan_part_kernel <<<1, 256, 0, s_side>>>(part, nb, rowptr, n);
    add_off_kernel   <<<(n + 255) / 256, 256, 0, s_side>>>(part, n, rowptr, cursor);
    fill_kernel      <<<eb4, 256, 0, s_side>>>(ei, e, cursor, col);
    cudaEventRecord(ev_join, s_side);

    // ---- main: gemm1 (needs only deg) ----
    gemm_f16_kernel<FH, false><<<(n + 63) / 64, 256, smem1>>>(x, W1, deg, hp1, n);

    // ---- join, then agg1 / gemm2 / agg2 ----
    cudaStreamWaitEvent(0, ev_join, 0);
    {
        int warps = (n + 1) / 2;
        aggregate_kernel<FH, true, true><<<(warps * 32 + 255) / 256, 256>>>(rowptr, col, hp1, deg, b1, h1, n);
    }
    gemm_f16_kernel<FO, true><<<(n + 63) / 64, 256, smem2>>>(h1, W2, deg, hp2, n);
    {
        int warps = (n + 3) / 4;
        aggregate_kernel<FO, false, false><<<(warps * 32 + 255) / 256, 256>>>(rowptr, col, hp2, deg, b2, out, n);
    }
}

// round 17
// speedup vs baseline: 1.1211x; 1.0312x over previous
#include <cuda_runtime.h>
#include <cuda_fp16.h>
#include <cstdint>

#define NV 50000
#define NE 800000
#define FIN 128
#define FH  128
#define FO  64

// ---------------- scratch (no allocs allowed) ----------------
static __device__ int    g_is64;
static __device__ int    g_deg   [NV];
static __device__ int    g_rowptr[NV + 1];
static __device__ int    g_cursor[NV];
static __device__ int    g_col   [NE];
static __device__ int    g_part  [64];
static __device__ __align__(16) __half g_hp1[(size_t)NV * FH];   // dinv-prescaled x@W1   (fp16)
static __device__ __align__(16) __half g_h1 [(size_t)NV * FH];   // layer-1 activation    (fp16)
static __device__ __align__(16) __half g_hp2[(size_t)NV * FO];   // dinv-prescaled h1@W2  (fp16)

// ---------------- edge-index dtype probe ----------------
// If edge_index is int64 (LE, values < 2^31), every odd int32 word is 0.
__global__ void probe_kernel(const int* __restrict__ raw, int* __restrict__ is64) {
    int v = raw[2 * threadIdx.x + 1];
    int any = __syncthreads_or(v != 0);
    if (threadIdx.x == 0) *is64 = (any == 0) ? 1 : 0;
}

// count dst degrees straight from raw edge buffer (deg pre-zeroed)
__global__ void count_deg_kernel(const int* __restrict__ raw, int e,
                                 const int* __restrict__ is64f,
                                 int* __restrict__ deg) {
    int i = blockIdx.x * blockDim.x + threadIdx.x;
    if (i >= e) return;
    int d = (*is64f) ? raw[2 * ((size_t)e + i)] : raw[(size_t)e + i];
    atomicAdd(&deg[d], 1);
}

// ---------------- scan phase 1: block-local exclusive + block totals ----------------
__global__ void scan_block_kernel(const int* __restrict__ deg, int n,
                                  int* __restrict__ rowptr, int* __restrict__ part)
{
    __shared__ int sm[1024];
    int i = blockIdx.x * 1024 + threadIdx.x;
    int v = (i < n) ? deg[i] : 0;
    sm[threadIdx.x] = v;
    __syncthreads();
    for (int off = 1; off < 1024; off <<= 1) {
        int t = (threadIdx.x >= (unsigned)off) ? sm[threadIdx.x - off] : 0;
        __syncthreads();
        sm[threadIdx.x] += t;
        __syncthreads();
    }
    if (i < n) rowptr[i] = sm[threadIdx.x] - v;      // block-local exclusive
    if (threadIdx.x == 1023) part[blockIdx.x] = sm[1023];
}

// ---------------- scan phase 2 (fused): each block re-scans the <=64 partials, applies offset ----------------
__global__ void add_off_kernel(const int* __restrict__ part, int nb, int n,
                               int* __restrict__ rowptr, int* __restrict__ cursor)
{
    __shared__ int pex[64];       // exclusive prefix of block partials
    __shared__ int ptot;
    if (threadIdx.x < 32) {
        int a = (threadIdx.x      < nb) ? part[threadIdx.x]      : 0;
        int b = (threadIdx.x + 32 < nb) ? part[threadIdx.x + 32] : 0;
        int va = a;
#pragma unroll
        for (int off = 1; off < 32; off <<= 1) {
            int t = __shfl_up_sync(0xFFFFFFFFu, va, off);
            if ((threadIdx.x & 31) >= (unsigned)off) va += t;
        }
        int sum_a = __shfl_sync(0xFFFFFFFFu, va, 31);   // total of first 32 (all lanes)
        int vb = b;
#pragma unroll
        for (int off = 1; off < 32; off <<= 1) {
            int t = __shfl_up_sync(0xFFFFFFFFu, vb, off);
            if ((threadIdx.x & 31) >= (unsigned)off) vb += t;
        }
        int totb = __shfl_sync(0xFFFFFFFFu, vb, 31);    // total of second 32 (all lanes — no divergence)
        pex[threadIdx.x]      = va - a;                  // exclusive
        pex[threadIdx.x + 32] = sum_a + vb - b;
        if (threadIdx.x == 31) ptot = sum_a + totb;
    }
    __syncthreads();
    int i = blockIdx.x * blockDim.x + threadIdx.x;
    if (i < n) {
        int r = rowptr[i] + pex[i >> 10];
        rowptr[i] = r;
        cursor[i] = r;
    }
    if (blockIdx.x == 0 && threadIdx.x == 0) rowptr[n] = ptot;
}

// ---------------- CSR fill: col[pos] = src, grouped by dst ----------------
__global__ void fill_kernel(const int* __restrict__ raw, int e,
                            const int* __restrict__ is64f,
                            int* __restrict__ cursor, int* __restrict__ col)
{
    int i = blockIdx.x * blockDim.x + threadIdx.x;
    if (i >= e) return;
    int s, d;
    if (*is64f) {
        s = raw[2 * (size_t)i];
        d = raw[2 * ((size_t)e + i)];
    } else {
        s = raw[i];
        d = raw[(size_t)e + i];
    }
    int pos = atomicAdd(&cursor[d], 1);
    col[pos] = s;
}

// ---------------- fp16 mma helper ----------------
__device__ __forceinline__ void mma_f16(float* d,
    uint32_t a0, uint32_t a1, uint32_t a2, uint32_t a3,
    uint32_t b0, uint32_t b1)
{
    asm volatile("mma.sync.aligned.m16n8k16.row.col.f32.f16.f16.f32 "
        "{%0,%1,%2,%3}, {%4,%5,%6,%7}, {%8,%9}, {%0,%1,%2,%3};"
        : "+f"(d[0]), "+f"(d[1]), "+f"(d[2]), "+f"(d[3])
        : "r"(a0), "r"(a1), "r"(a2), "r"(a3), "r"(b0), "r"(b1));
}

// ---------------- fp16 tensor-core GEMM: hp[row] = fp16( dinv[row] * (A[row] @ W) ) ----------------
// Block tile 64 x OUT, K=128, 8 warps. A fp32 or fp16 per IN_HALF.
template<int OUT, bool IN_HALF>
__global__ __launch_bounds__(256) void gemm_f16_kernel(
    const void* __restrict__ Ain, const float* __restrict__ W,
    const int* __restrict__ deg, __half* __restrict__ hp, int n)
{
    constexpr int K       = 128;
    constexpr int TILE_M  = 64;
    constexpr int WARPS_M = 2;
    constexpr int WM      = TILE_M / WARPS_M;  // 32
    constexpr int WN      = OUT / 4;           // 32 or 16
    constexpr int MT      = WM / 16;           // 2
    constexpr int NT      = WN / 8;            // 4 or 2
    constexpr int SK      = K / 2 + 4;         // 68 words

    extern __shared__ uint32_t smem[];
    uint32_t* Xs = smem;                  // [TILE_M][SK]
    uint32_t* Wt = smem + TILE_M * SK;    // [OUT][SK]

    const int t    = threadIdx.x;
    const int lane = t & 31;
    const int wid  = t >> 5;
    const int wm   = wid % WARPS_M;
    const int wn   = wid / WARPS_M;
    const int lr   = lane >> 2;
    const int lc   = lane & 3;

    const int row0 = blockIdx.x * TILE_M;

    // W [K][OUT] fp32 -> Wt [OUT][K/2] packed half2 (transpose)
    for (int i = t; i < (K / 2) * OUT; i += 256) {
        int k2 = i / OUT;
        int c  = i % OUT;
        __half2 h = __floats2half2_rn(W[(size_t)(2 * k2) * OUT + c],
                                      W[(size_t)(2 * k2 + 1) * OUT + c]);
        Wt[c * SK + k2] = *(uint32_t*)&h;
    }
    if (IN_HALF) {
        const uint4* A8 = (const uint4*)Ain;
        for (int i = t; i < TILE_M * (K / 8); i += 256) {
            int r  = i / (K / 8);
            int c8 = i % (K / 8);
            int gr = row0 + r;
            uint32_t* p = &Xs[r * SK + c8 * 4];
            if (gr < n) {
                uint4 v = A8[(size_t)gr * (K / 8) + c8];
                p[0] = v.x; p[1] = v.y; p[2] = v.z; p[3] = v.w;
            } else {
                p[0] = 0; p[1] = 0; p[2] = 0; p[3] = 0;
            }
        }
    } else {
        const float4* A4 = (const float4*)Ain;
        for (int i = t; i < TILE_M * (K / 4); i += 256) {
            int r  = i / (K / 4);
            int c4 = i % (K / 4);
            int gr = row0 + r;
            float4 v = (gr < n) ? A4[(size_t)gr * (K / 4) + c4]
                                : make_float4(0.f, 0.f, 0.f, 0.f);
            __half2 h0 = __floats2half2_rn(v.x, v.y);
            __half2 h1 = __floats2half2_rn(v.z, v.w);
            Xs[r * SK + c4 * 2]     = *(uint32_t*)&h0;
            Xs[r * SK + c4 * 2 + 1] = *(uint32_t*)&h1;
        }
    }
    __syncthreads();

    float d[MT][NT][4];
#pragma unroll
    for (int mt = 0; mt < MT; mt++)
#pragma unroll
        for (int nt = 0; nt < NT; nt++) {
            d[mt][nt][0] = 0.f; d[mt][nt][1] = 0.f;
            d[mt][nt][2] = 0.f; d[mt][nt][3] = 0.f;
        }

    const int r0 = wm * WM;
    const int c0 = wn * WN;

#pragma unroll
    for (int k0 = 0; k0 < K; k0 += 16) {
        const int w0 = k0 / 2;
        uint32_t b[NT][2];
#pragma unroll
        for (int nt = 0; nt < NT; nt++) {
            int bc = c0 + nt * 8 + lr;
            b[nt][0] = Wt[bc * SK + w0 + lc];
            b[nt][1] = Wt[bc * SK + w0 + 4 + lc];
        }
#pragma unroll
        for (int mt = 0; mt < MT; mt++) {
            int ar = r0 + mt * 16 + lr;
            uint32_t a0 = Xs[ar       * SK + w0 + lc];
            uint32_t a1 = Xs[(ar + 8) * SK + w0 + lc];
            uint32_t a2 = Xs[ar       * SK + w0 + 4 + lc];
            uint32_t a3 = Xs[(ar + 8) * SK + w0 + 4 + lc];
#pragma unroll
            for (int nt = 0; nt < NT; nt++)
                mma_f16(d[mt][nt], a0, a1, a2, a3, b[nt][0], b[nt][1]);
        }
    }

#pragma unroll
    for (int mt = 0; mt < MT; mt++) {
        int gr0 = row0 + r0 + mt * 16 + lr;
        int gr1 = gr0 + 8;
        float dv0 = (gr0 < n) ? rsqrtf((float)(deg[gr0] + 1)) : 0.f;
        float dv1 = (gr1 < n) ? rsqrtf((float)(deg[gr1] + 1)) : 0.f;
#pragma unroll
        for (int nt = 0; nt < NT; nt++) {
            int gc = c0 + nt * 8 + 2 * lc;
            if (gr0 < n) {
                __half2 h = __floats2half2_rn(d[mt][nt][0] * dv0, d[mt][nt][1] * dv0);
                ((uint32_t*)hp)[(size_t)gr0 * (OUT / 2) + gc / 2] = *(uint32_t*)&h;
            }
            if (gr1 < n) {
                __half2 h = __floats2half2_rn(d[mt][nt][2] * dv1, d[mt][nt][3] * dv1);
                ((uint32_t*)hp)[(size_t)gr1 * (OUT / 2) + gc / 2] = *(uint32_t*)&h;
            }
        }
    }
}

// ---------------- aggregate: out[d] = act(dinv[d]*(hp[d] + sum_src hp[src]) + b) ----------------
__device__ __forceinline__ void acc8(float* a, uint4 v) {
    const __half2* ph = (const __half2*)&v;
#pragma unroll
    for (int j = 0; j < 4; j++) {
        float2 f = __half22float2(ph[j]);
        a[2 * j]     += f.x;
        a[2 * j + 1] += f.y;
    }
}

template<int F, bool RELU, bool OUT_HALF>
__global__ __launch_bounds__(256) void aggregate_kernel(
    const int* __restrict__ rowptr, const int* __restrict__ col,
    const __half* __restrict__ hp, const int* __restrict__ deg,
    const float* __restrict__ b, void* __restrict__ out, int n)
{
    constexpr int LPR = F / 8;        // lanes per node row (16 or 8)
    constexpr int SUB = 32 / LPR;     // nodes per warp (2 or 4)
    const int warp = (blockIdx.x * blockDim.x + threadIdx.x) >> 5;
    const int lane = threadIdx.x & 31;
    const int node = warp * SUB + lane / LPR;
    const int li   = lane % LPR;
    if (node >= n) return;

    const uint4* hp4 = (const uint4*)hp;

    float a0[8] = {0,0,0,0,0,0,0,0};
    float a1[8] = {0,0,0,0,0,0,0,0};

    acc8(a0, hp4[(size_t)node * LPR + li]);   // self-loop term (prescaled)

    int e  = rowptr[node];
    int e1 = rowptr[node + 1];

    for (; e + 8 <= e1; e += 8) {
        int s0 = __ldg(&col[e]);
        int s1 = __ldg(&col[e + 1]);
        int s2 = __ldg(&col[e + 2]);
        int s3 = __ldg(&col[e + 3]);
        int s4 = __ldg(&col[e + 4]);
        int s5 = __ldg(&col[e + 5]);
        int s6 = __ldg(&col[e + 6]);
        int s7 = __ldg(&col[e + 7]);
        uint4 v0 = hp4[(size_t)s0 * LPR + li];
        uint4 v1 = hp4[(size_t)s1 * LPR + li];
        uint4 v2 = hp4[(size_t)s2 * LPR + li];
        uint4 v3 = hp4[(size_t)s3 * LPR + li];
        uint4 v4 = hp4[(size_t)s4 * LPR + li];
        uint4 v5 = hp4[(size_t)s5 * LPR + li];
        uint4 v6 = hp4[(size_t)s6 * LPR + li];
        uint4 v7 = hp4[(size_t)s7 * LPR + li];
        acc8(a0, v0); acc8(a1, v1); acc8(a0, v2); acc8(a1, v3);
        acc8(a0, v4); acc8(a1, v5); acc8(a0, v6); acc8(a1, v7);
    }
    for (; e + 2 <= e1; e += 2) {
        int s0 = __ldg(&col[e]);
        int s1 = __ldg(&col[e + 1]);
        uint4 v0 = hp4[(size_t)s0 * LPR + li];
        uint4 v1 = hp4[(size_t)s1 * LPR + li];
        acc8(a0, v0); acc8(a1, v1);
    }
    for (; e < e1; e++) {
        acc8(a0, hp4[(size_t)__ldg(&col[e]) * LPR + li]);
    }
#pragma unroll
    for (int j = 0; j < 8; j++) a0[j] += a1[j];

    float dv = rsqrtf((float)(deg[node] + 1));
    const float4* b4 = (const float4*)b;
    float4 bv0 = b4[li * 2];
    float4 bv1 = b4[li * 2 + 1];
    float o[8];
    o[0] = fmaf(a0[0], dv, bv0.x);
    o[1] = fmaf(a0[1], dv, bv0.y);
    o[2] = fmaf(a0[2], dv, bv0.z);
    o[3] = fmaf(a0[3], dv, bv0.w);
    o[4] = fmaf(a0[4], dv, bv1.x);
    o[5] = fmaf(a0[5], dv, bv1.y);
    o[6] = fmaf(a0[6], dv, bv1.z);
    o[7] = fmaf(a0[7], dv, bv1.w);
    if (RELU) {
#pragma unroll
        for (int j = 0; j < 8; j++) o[j] = fmaxf(o[j], 0.f);
    }
    if (OUT_HALF) {
        __half2 h0 = __floats2half2_rn(o[0], o[1]);
        __half2 h1 = __floats2half2_rn(o[2], o[3]);
        __half2 h2 = __floats2half2_rn(o[4], o[5]);
        __half2 h3 = __floats2half2_rn(o[6], o[7]);
        uint4 pk;
        pk.x = *(uint32_t*)&h0; pk.y = *(uint32_t*)&h1;
        pk.z = *(uint32_t*)&h2; pk.w = *(uint32_t*)&h3;
        ((uint4*)out)[(size_t)node * LPR + li] = pk;
    } else {
        float4* out4 = (float4*)out;
        out4[(size_t)node * (F / 4) + li * 2]     = make_float4(o[0], o[1], o[2], o[3]);
        out4[(size_t)node * (F / 4) + li * 2 + 1] = make_float4(o[4], o[5], o[6], o[7]);
    }
}

// ---------------- launcher ----------------
extern "C" void kernel_launch(void* const* d_in, const int* in_sizes, int n_in,
                              void* d_out, int out_size)
{
    const float* x   = (const float*)d_in[0];
    const int*   ei  = (const int*)d_in[1];     // int32 OR int64 raw words (probed)
    const float* W1  = (const float*)d_in[2];
    const float* b1  = (const float*)d_in[3];
    const float* W2  = (const float*)d_in[4];
    const float* b2  = (const float*)d_in[5];
    float*       out = (float*)d_out;

    const int n = in_sizes[0] / FIN;   // 50000
    const int e = in_sizes[1] / 2;     // 800000

    void *p_is64, *p_deg, *p_rowptr, *p_cursor, *p_col, *p_part, *p_hp1, *p_h1, *p_hp2;
    cudaGetSymbolAddress(&p_is64,   g_is64);
    cudaGetSymbolAddress(&p_deg,    g_deg);
    cudaGetSymbolAddress(&p_rowptr, g_rowptr);
    cudaGetSymbolAddress(&p_cursor, g_cursor);
    cudaGetSymbolAddress(&p_col,    g_col);
    cudaGetSymbolAddress(&p_part,   g_part);
    cudaGetSymbolAddress(&p_hp1,    g_hp1);
    cudaGetSymbolAddress(&p_h1,     g_h1);
    cudaGetSymbolAddress(&p_hp2,    g_hp2);
    int*    is64   = (int*)p_is64;
    int*    deg    = (int*)p_deg;
    int*    rowptr = (int*)p_rowptr;
    int*    cursor = (int*)p_cursor;
    int*    col    = (int*)p_col;
    int*    part   = (int*)p_part;
    __half* hp1    = (__half*)p_hp1;
    __half* h1     = (__half*)p_h1;
    __half* hp2    = (__half*)p_hp2;

    // one-time side stream + events (created on first, non-captured, call)
    static cudaStream_t s_side = nullptr;
    static cudaEvent_t  ev_fork = nullptr, ev_join = nullptr;
    if (s_side == nullptr) {
        cudaStreamCreateWithFlags(&s_side, cudaStreamNonBlocking);
        cudaEventCreateWithFlags(&ev_fork, cudaEventDisableTiming);
        cudaEventCreateWithFlags(&ev_join, cudaEventDisableTiming);
    }

    constexpr int SK = 128 / 2 + 4;   // 68
    const int smem1 = (64 * SK + FH * SK) * (int)sizeof(uint32_t);  // 52224
    const int smem2 = (64 * SK + FO * SK) * (int)sizeof(uint32_t);  // 34816
    cudaFuncSetAttribute((const void*)gemm_f16_kernel<FH, false>, cudaFuncAttributeMaxDynamicSharedMemorySize, smem1);
    cudaFuncSetAttribute((const void*)gemm_f16_kernel<FO, true>,  cudaFuncAttributeMaxDynamicSharedMemorySize, smem2);

    const int nb = (n + 1023) / 1024;   // 49 partials (<=64)

    // ---- main: probe + degrees ----
    cudaMemsetAsync(deg, 0, n * sizeof(int));
    probe_kernel     <<<1, 256>>>(ei, is64);
    count_deg_kernel <<<(e + 255) / 256, 256>>>(ei, e, is64, deg);

    // ---- fork: CSR build on side stream (3 launches) ----
    cudaEventRecord(ev_fork, 0);
    cudaStreamWaitEvent(s_side, ev_fork, 0);
    scan_block_kernel<<<nb, 1024, 0, s_side>>>(deg, n, rowptr, part);
    add_off_kernel   <<<(n + 255) / 256, 256, 0, s_side>>>(part, nb, n, rowptr, cursor);
    fill_kernel      <<<(e + 255) / 256, 256, 0, s_side>>>(ei, e, is64, cursor, col);
    cudaEventRecord(ev_join, s_side);

    // ---- main: gemm1 (needs only deg) ----
    gemm_f16_kernel<FH, false><<<(n + 63) / 64, 256, smem1>>>(x, W1, deg, hp1, n);

    // ---- join, then agg1 / gemm2 / agg2 ----
    cudaStreamWaitEvent(0, ev_join, 0);
    {
        int warps = (n + 1) / 2;
        aggregate_kernel<FH, true, true><<<(warps * 32 + 255) / 256, 256>>>(rowptr, col, hp1, deg, b1, h1, n);
    }
    gemm_f16_kernel<FO, true><<<(n + 63) / 64, 256, smem2>>>(h1, W2, deg, hp2, n);
    {
        int warps = (n + 3) / 4;
        aggregate_kernel<FO, false, false><<<(warps * 32 + 255) / 256, 256>>>(rowptr, col, hp2, deg, b2, out, n);
    }
}